// round 14
// baseline (speedup 1.0000x reference)
#include <cuda_runtime.h>
#include <cuda_fp16.h>

// TriMip encoding v7: fused 2-kernel build + 4-lane-per-item sampler.
// Lanes (c,h) per (point,plane): one load instruction covers the 64B
// contiguous v00|v10 span -> L1tex merges lines within the instruction
// (2.5 wavefronts/tap vs 4). Levels 4..7 staged in 130.5KB dynamic smem.

#define NLV 8

__device__ float g_l1[3145728];           // fp32 level-1 scratch (12.6 MB)
__device__ __half g_pyrh[16776960];       // fp16 pyramid levels 0..7 (33.5 MB)

__constant__ int c_offh[8] = {0, 12582912, 15728640, 16515072, 16711680,
                              16760832, 16773120, 16776192};

#define L4_OFF      16711680              // c_offh[4]
#define SMEM_HALVES 65280                 // levels 4..7 halves (130,560 B)

// ---------------------------------------------------------------------------
// K1: one thread per level-1 quad (3*256*256*4 threads).
__global__ void __launch_bounds__(256) k1_l0_l1(const float* __restrict__ fm) {
    int t = blockIdx.x * blockDim.x + threadIdx.x;
    const int total = 3 * 256 * 256 * 4;
    if (t >= total) return;
    int q   = t & 3;
    int idx = t >> 2;
    int xo  = idx & 255; idx >>= 8;
    int yo  = idx & 255;
    int pl  = idx >> 8;

    const float4* src = (const float4*)fm;
    int y0 = 2 * yo, x0 = 2 * xo;
    long b00 = ((long)(pl * 512 + y0) * 512 + x0) * 4 + q;
    float4 a = __ldg(src + b00);
    float4 b = __ldg(src + b00 + 4);
    float4 c = __ldg(src + b00 + 512 * 4);
    float4 d = __ldg(src + b00 + 512 * 4 + 4);

    uint2* l0h = (uint2*)g_pyrh;
    uint2 pa, pb, pc, pd;
    #define PACKQ(dst, v) { __half2 _h0 = __floats2half2_rn((v).x, (v).y); \
                            __half2 _h1 = __floats2half2_rn((v).z, (v).w); \
                            (dst).x = *(unsigned*)&_h0; (dst).y = *(unsigned*)&_h1; }
    PACKQ(pa, a); PACKQ(pb, b); PACKQ(pc, c); PACKQ(pd, d);
    l0h[b00]               = pa;
    l0h[b00 + 4]           = pb;
    l0h[b00 + 512 * 4]     = pc;
    l0h[b00 + 512 * 4 + 4] = pd;

    float4 o;
    o.x = (a.x + b.x + c.x + d.x) * 0.25f;
    o.y = (a.y + b.y + c.y + d.y) * 0.25f;
    o.z = (a.z + b.z + c.z + d.z) * 0.25f;
    o.w = (a.w + b.w + c.w + d.w) * 0.25f;

    long l1i = ((long)(pl * 256 + yo) * 256 + xo) * 4 + q;
    ((float4*)g_l1)[l1i] = o;
    uint2 po; PACKQ(po, o);
    ((uint2*)(g_pyrh + c_offh[1]))[l1i] = po;
    #undef PACKQ
}

// ---------------------------------------------------------------------------
// K2: levels 2..7 from fp32 level1 by flat box mean.
__global__ void __launch_bounds__(256) k2_levels(void) {
    const int PT_L2 = 3 * 128 * 128 * 4;
    const int PT_L3 = 3 * 64 * 64 * 4;
    const int PT_L4 = 3 * 32 * 32 * 4;
    const int PT_TOTAL = PT_L2 + PT_L3 + PT_L4;
    const int PW_L5 = 3 * 16 * 16 * 4;
    const int PW_L6 = 3 * 8 * 8 * 4;
    const int PW_L7 = 3 * 4 * 4 * 4;

    int t = blockIdx.x * blockDim.x + threadIdx.x;
    const float4* l1 = (const float4*)g_l1;

    if (t < PT_TOTAL) {
        int l, rem = t;
        if (rem < PT_L2) l = 2;
        else if (rem < PT_L2 + PT_L3) { l = 3; rem -= PT_L2; }
        else { l = 4; rem -= PT_L2 + PT_L3; }
        int S = 512 >> l;
        int B = 1 << (l - 1);
        int q = rem & 3; int idx = rem >> 2;
        int x = idx % S; idx /= S;
        int y = idx % S;
        int pl = idx / S;

        float4 acc = make_float4(0.f, 0.f, 0.f, 0.f);
        int ybase = y * B, xbase = x * B;
        for (int by = 0; by < B; by++) {
            long row = ((long)(pl * 256 + ybase + by) * 256 + xbase) * 4 + q;
            for (int bx = 0; bx < B; bx++) {
                float4 v = __ldg(l1 + row + bx * 4);
                acc.x += v.x; acc.y += v.y; acc.z += v.z; acc.w += v.w;
            }
        }
        float inv = 1.0f / (float)(B * B);
        acc.x *= inv; acc.y *= inv; acc.z *= inv; acc.w *= inv;
        __half2 h0 = __floats2half2_rn(acc.x, acc.y);
        __half2 h1 = __floats2half2_rn(acc.z, acc.w);
        uint2 po; po.x = *(unsigned*)&h0; po.y = *(unsigned*)&h1;
        ((uint2*)(g_pyrh + c_offh[l]))[((long)(pl * S + y) * S + x) * 4 + q] = po;
        return;
    }

    int w = (t - PT_TOTAL) >> 5;
    int lane = t & 31;
    int l, rem = w;
    if (rem < PW_L5) l = 5;
    else if (rem < PW_L5 + PW_L6) { l = 6; rem -= PW_L5; }
    else if (rem < PW_L5 + PW_L6 + PW_L7) { l = 7; rem -= PW_L5 + PW_L6; }
    else return;

    int S = 512 >> l;
    int B = 1 << (l - 1);
    int nbox = B * B;
    int q = rem & 3; int idx = rem >> 2;
    int x = idx % S; idx /= S;
    int y = idx % S;
    int pl = idx / S;

    float4 acc = make_float4(0.f, 0.f, 0.f, 0.f);
    for (int j = lane; j < nbox; j += 32) {
        int by = j / B, bx = j - by * B;
        long e = ((long)(pl * 256 + y * B + by) * 256 + x * B + bx) * 4 + q;
        float4 v = __ldg(l1 + e);
        acc.x += v.x; acc.y += v.y; acc.z += v.z; acc.w += v.w;
    }
    #pragma unroll
    for (int off = 16; off > 0; off >>= 1) {
        acc.x += __shfl_down_sync(0xffffffffu, acc.x, off);
        acc.y += __shfl_down_sync(0xffffffffu, acc.y, off);
        acc.z += __shfl_down_sync(0xffffffffu, acc.z, off);
        acc.w += __shfl_down_sync(0xffffffffu, acc.w, off);
    }
    if (lane == 0) {
        float inv = 1.0f / (float)nbox;
        acc.x *= inv; acc.y *= inv; acc.z *= inv; acc.w *= inv;
        __half2 h0 = __floats2half2_rn(acc.x, acc.y);
        __half2 h1 = __floats2half2_rn(acc.z, acc.w);
        uint2 po; po.x = *(unsigned*)&h0; po.y = *(unsigned*)&h1;
        ((uint2*)(g_pyrh + c_offh[l]))[((long)(pl * S + y) * S + x) * 4 + q] = po;
    }
}

// ---------------------------------------------------------------------------
// Dummy no-op: shifts the ncu capture slot so slot 5 = trimip_sample.
__global__ void dummy_slot(void) {}

// ---------------------------------------------------------------------------
// Sampler v7: 4 lanes per (point,plane): sub bit0 = h (feature half),
// bit1 = c (left/right texel). Per level each lane does 2 loads (row iy0,
// row iy1 of its texel column); v00|v10 merge into shared 128B lines within
// one instruction. shfl_xor(2) combines c-partners; every lane stores its
// 16B quarter of the 64B output -> fully coalesced.
__global__ void __launch_bounds__(1024, 1) trimip_sample(
    const float* __restrict__ x,
    const float* __restrict__ level,
    float* __restrict__ out,
    int N)
{
    extern __shared__ __align__(16) __half s_top[];   // SMEM_HALVES

    // stage levels 4..7 (contiguous in g_pyrh from L4_OFF)
    {
        const float4* src = (const float4*)(g_pyrh + L4_OFF);
        float4* dst = (float4*)s_top;
        for (int i = threadIdx.x; i < SMEM_HALVES / 8; i += blockDim.x)
            dst[i] = __ldg(src + i);
    }
    __syncthreads();

    int total = N * 12;
    int stride = gridDim.x * blockDim.x;

    for (int t = blockIdx.x * blockDim.x + threadIdx.x; t < total; t += stride) {
        int item = t >> 2;          // (point, plane)
        int sub  = t & 3;
        int h = sub & 1;            // feature half
        int c = sub >> 1;           // texel column (0 = ix0, 1 = ix1)
        int n = item / 3;
        int p = item - n * 3;

        float xc0 = __ldg(&x[3 * n + 0]);
        float xc1 = __ldg(&x[3 * n + 1]);
        float xc2 = __ldg(&x[3 * n + 2]);
        float u = (p == 0) ? xc1 : xc0;
        float v = (p == 2) ? xc1 : xc2;

        float lvl = fminf(fmaxf(__ldg(&level[n]), 0.0f), (float)(NLV - 1));
        int   l0  = min((int)lvl, NLV - 2);
        float fr  = lvl - (float)l0;

        float acc[8] = {0.f, 0.f, 0.f, 0.f, 0.f, 0.f, 0.f, 0.f};

        #pragma unroll
        for (int k = 0; k < 2; k++) {
            int   l = l0 + k;
            float w = k ? fr : (1.0f - fr);
            int   S = 512 >> l;

            float px = u * (float)S - 0.5f;
            float py = v * (float)S - 0.5f;
            float fx = floorf(px);
            float fy = floorf(py);
            int ix0 = (int)fx;
            int iy0 = (int)fy;
            int ix1 = min(ix0 + 1, S - 1);
            int iy1 = min(iy0 + 1, S - 1);
            ix0 = max(ix0, 0);
            iy0 = max(iy0, 0);
            float ax = px - fx;
            float ay = py - fy;

            int   ixc = c ? ix1 : ix0;
            float bx  = c ? ax  : 1.0f - ax;

            long e0 = (long)(iy0 * S + ixc) * 16 + h * 8;
            long e1 = (long)(iy1 * S + ixc) * 16 + h * 8;

            float4 r0, r1;
            if (l >= 4) {
                const __half* b = s_top + (c_offh[l] - L4_OFF)
                                + (long)p * S * S * 16;
                r0 = *(const float4*)(b + e0);
                r1 = *(const float4*)(b + e1);
            } else {
                const __half* b = g_pyrh + c_offh[l]
                                + (long)p * S * S * 16;
                r0 = __ldg((const float4*)(b + e0));
                r1 = __ldg((const float4*)(b + e1));
            }

            float w0 = w * bx * (1.0f - ay);
            float w1 = w * bx * ay;

            #define ACCQ(wgt, raw) { const __half2* _hp = (const __half2*)&(raw); \
                float2 _f0 = __half22float2(_hp[0]); float2 _f1 = __half22float2(_hp[1]); \
                float2 _f2 = __half22float2(_hp[2]); float2 _f3 = __half22float2(_hp[3]); \
                acc[0] = fmaf(wgt, _f0.x, acc[0]); acc[1] = fmaf(wgt, _f0.y, acc[1]); \
                acc[2] = fmaf(wgt, _f1.x, acc[2]); acc[3] = fmaf(wgt, _f1.y, acc[3]); \
                acc[4] = fmaf(wgt, _f2.x, acc[4]); acc[5] = fmaf(wgt, _f2.y, acc[5]); \
                acc[6] = fmaf(wgt, _f3.x, acc[6]); acc[7] = fmaf(wgt, _f3.y, acc[7]); }
            ACCQ(w0, r0); ACCQ(w1, r1);
            #undef ACCQ
        }

        // combine c-partners (lanes differ in bit 1); tail cuts on 4-lane
        // groups so xor-2 partners are always jointly active.
        unsigned m = __activemask();
        #pragma unroll
        for (int i = 0; i < 8; i++)
            acc[i] += __shfl_xor_sync(m, acc[i], 2);

        float4 lo = make_float4(acc[0], acc[1], acc[2], acc[3]);
        float4 hi = make_float4(acc[4], acc[5], acc[6], acc[7]);
        float4 sv = c ? hi : lo;
        ((float4*)(out + (long)n * 48 + p * 16 + h * 8))[c] = sv;
    }
}

// ---------------------------------------------------------------------------
extern "C" void kernel_launch(void* const* d_in, const int* in_sizes, int n_in,
                              void* d_out, int out_size) {
    const float* x     = (const float*)d_in[0];
    const float* level = (const float*)d_in[1];
    const float* fm    = (const float*)d_in[2];
    float* out = (float*)d_out;
    int N = in_sizes[0] / 3;

    // K1: level 0 convert + level 1 build
    {
        int total = 3 * 256 * 256 * 4;
        k1_l0_l1<<<(total + 255) / 256, 256>>>(fm);
    }
    // K2: levels 2..7
    {
        int total_threads = 258048 + (3072 + 768 + 192) * 32;
        k2_levels<<<(total_threads + 255) / 256, 256>>>();
    }
    // Dummy: aligns ncu slot 5 onto the sampler
    dummy_slot<<<1, 1>>>();
    // S: persistent sampler, 130.5 KB dynamic smem
    {
        const int smem_bytes = SMEM_HALVES * 2;   // 130,560
        cudaFuncSetAttribute(trimip_sample,
                             cudaFuncAttributeMaxDynamicSharedMemorySize,
                             smem_bytes);
        trimip_sample<<<148, 1024, smem_bytes>>>(x, level, out, N);
    }
}

// round 15
// speedup vs baseline: 1.2311x; 1.2311x over previous
#include <cuda_runtime.h>
#include <cuda_fp16.h>

// TriMip encoding v8: fused 2-kernel build + role-fixed 4-lane sampler.
// Thread role (c,h) = tid&3 (no divisions); one point per thread-quad,
// 3 planes in an inner loop -> point setup amortized over 6 taps while
// keeping v7's 2-load/tap 64B-span merging. Levels 4..7 in 130.5KB smem.

#define NLV 8

__device__ float g_l1[3145728];           // fp32 level-1 scratch (12.6 MB)
__device__ __half g_pyrh[16776960];       // fp16 pyramid levels 0..7 (33.5 MB)

__constant__ int c_offh[8] = {0, 12582912, 15728640, 16515072, 16711680,
                              16760832, 16773120, 16776192};

#define L4_OFF      16711680              // c_offh[4]
#define SMEM_HALVES 65280                 // levels 4..7 halves (130,560 B)

// ---------------------------------------------------------------------------
// K1: one thread per level-1 quad (3*256*256*4 threads).
__global__ void __launch_bounds__(256) k1_l0_l1(const float* __restrict__ fm) {
    int t = blockIdx.x * blockDim.x + threadIdx.x;
    const int total = 3 * 256 * 256 * 4;
    if (t >= total) return;
    int q   = t & 3;
    int idx = t >> 2;
    int xo  = idx & 255; idx >>= 8;
    int yo  = idx & 255;
    int pl  = idx >> 8;

    const float4* src = (const float4*)fm;
    int y0 = 2 * yo, x0 = 2 * xo;
    long b00 = ((long)(pl * 512 + y0) * 512 + x0) * 4 + q;
    float4 a = __ldg(src + b00);
    float4 b = __ldg(src + b00 + 4);
    float4 c = __ldg(src + b00 + 512 * 4);
    float4 d = __ldg(src + b00 + 512 * 4 + 4);

    uint2* l0h = (uint2*)g_pyrh;
    uint2 pa, pb, pc, pd;
    #define PACKQ(dst, v) { __half2 _h0 = __floats2half2_rn((v).x, (v).y); \
                            __half2 _h1 = __floats2half2_rn((v).z, (v).w); \
                            (dst).x = *(unsigned*)&_h0; (dst).y = *(unsigned*)&_h1; }
    PACKQ(pa, a); PACKQ(pb, b); PACKQ(pc, c); PACKQ(pd, d);
    l0h[b00]               = pa;
    l0h[b00 + 4]           = pb;
    l0h[b00 + 512 * 4]     = pc;
    l0h[b00 + 512 * 4 + 4] = pd;

    float4 o;
    o.x = (a.x + b.x + c.x + d.x) * 0.25f;
    o.y = (a.y + b.y + c.y + d.y) * 0.25f;
    o.z = (a.z + b.z + c.z + d.z) * 0.25f;
    o.w = (a.w + b.w + c.w + d.w) * 0.25f;

    long l1i = ((long)(pl * 256 + yo) * 256 + xo) * 4 + q;
    ((float4*)g_l1)[l1i] = o;
    uint2 po; PACKQ(po, o);
    ((uint2*)(g_pyrh + c_offh[1]))[l1i] = po;
    #undef PACKQ
}

// ---------------------------------------------------------------------------
// K2: levels 2..7 from fp32 level1 by flat box mean.
__global__ void __launch_bounds__(256) k2_levels(void) {
    const int PT_L2 = 3 * 128 * 128 * 4;
    const int PT_L3 = 3 * 64 * 64 * 4;
    const int PT_L4 = 3 * 32 * 32 * 4;
    const int PT_TOTAL = PT_L2 + PT_L3 + PT_L4;
    const int PW_L5 = 3 * 16 * 16 * 4;
    const int PW_L6 = 3 * 8 * 8 * 4;
    const int PW_L7 = 3 * 4 * 4 * 4;

    int t = blockIdx.x * blockDim.x + threadIdx.x;
    const float4* l1 = (const float4*)g_l1;

    if (t < PT_TOTAL) {
        int l, rem = t;
        if (rem < PT_L2) l = 2;
        else if (rem < PT_L2 + PT_L3) { l = 3; rem -= PT_L2; }
        else { l = 4; rem -= PT_L2 + PT_L3; }
        int S = 512 >> l;
        int B = 1 << (l - 1);
        int q = rem & 3; int idx = rem >> 2;
        int x = idx % S; idx /= S;
        int y = idx % S;
        int pl = idx / S;

        float4 acc = make_float4(0.f, 0.f, 0.f, 0.f);
        int ybase = y * B, xbase = x * B;
        for (int by = 0; by < B; by++) {
            long row = ((long)(pl * 256 + ybase + by) * 256 + xbase) * 4 + q;
            for (int bx = 0; bx < B; bx++) {
                float4 v = __ldg(l1 + row + bx * 4);
                acc.x += v.x; acc.y += v.y; acc.z += v.z; acc.w += v.w;
            }
        }
        float inv = 1.0f / (float)(B * B);
        acc.x *= inv; acc.y *= inv; acc.z *= inv; acc.w *= inv;
        __half2 h0 = __floats2half2_rn(acc.x, acc.y);
        __half2 h1 = __floats2half2_rn(acc.z, acc.w);
        uint2 po; po.x = *(unsigned*)&h0; po.y = *(unsigned*)&h1;
        ((uint2*)(g_pyrh + c_offh[l]))[((long)(pl * S + y) * S + x) * 4 + q] = po;
        return;
    }

    int w = (t - PT_TOTAL) >> 5;
    int lane = t & 31;
    int l, rem = w;
    if (rem < PW_L5) l = 5;
    else if (rem < PW_L5 + PW_L6) { l = 6; rem -= PW_L5; }
    else if (rem < PW_L5 + PW_L6 + PW_L7) { l = 7; rem -= PW_L5 + PW_L6; }
    else return;

    int S = 512 >> l;
    int B = 1 << (l - 1);
    int nbox = B * B;
    int q = rem & 3; int idx = rem >> 2;
    int x = idx % S; idx /= S;
    int y = idx % S;
    int pl = idx / S;

    float4 acc = make_float4(0.f, 0.f, 0.f, 0.f);
    for (int j = lane; j < nbox; j += 32) {
        int by = j / B, bx = j - by * B;
        long e = ((long)(pl * 256 + y * B + by) * 256 + x * B + bx) * 4 + q;
        float4 v = __ldg(l1 + e);
        acc.x += v.x; acc.y += v.y; acc.z += v.z; acc.w += v.w;
    }
    #pragma unroll
    for (int off = 16; off > 0; off >>= 1) {
        acc.x += __shfl_down_sync(0xffffffffu, acc.x, off);
        acc.y += __shfl_down_sync(0xffffffffu, acc.y, off);
        acc.z += __shfl_down_sync(0xffffffffu, acc.z, off);
        acc.w += __shfl_down_sync(0xffffffffu, acc.w, off);
    }
    if (lane == 0) {
        float inv = 1.0f / (float)nbox;
        acc.x *= inv; acc.y *= inv; acc.z *= inv; acc.w *= inv;
        __half2 h0 = __floats2half2_rn(acc.x, acc.y);
        __half2 h1 = __floats2half2_rn(acc.z, acc.w);
        uint2 po; po.x = *(unsigned*)&h0; po.y = *(unsigned*)&h1;
        ((uint2*)(g_pyrh + c_offh[l]))[((long)(pl * S + y) * S + x) * 4 + q] = po;
    }
}

// ---------------------------------------------------------------------------
// Dummy no-op: shifts the ncu capture slot so slot 5 = trimip_sample.
__global__ void dummy_slot(void) {}

// ---------------------------------------------------------------------------
// Sampler v8: thread-quad per point. sub = tid&3: h = sub&1 (feature half),
// c = sub>>1 (texel column). Point setup hoisted out of the 3-plane loop.
// Per tap each lane does 2 loads (rows iy0/iy1 of its column); the quad's
// 4 lanes span 64B contiguous per row -> L1tex merges lines in-instruction.
__global__ void __launch_bounds__(1024, 1) trimip_sample(
    const float* __restrict__ x,
    const float* __restrict__ level,
    float* __restrict__ out,
    int N)
{
    extern __shared__ __align__(16) __half s_top[];   // SMEM_HALVES

    // stage levels 4..7 (contiguous in g_pyrh from L4_OFF)
    {
        const float4* src = (const float4*)(g_pyrh + L4_OFF);
        float4* dst = (float4*)s_top;
        for (int i = threadIdx.x; i < SMEM_HALVES / 8; i += blockDim.x)
            dst[i] = __ldg(src + i);
    }
    __syncthreads();

    int tid = blockIdx.x * blockDim.x + threadIdx.x;
    int sub = tid & 3;
    int h = sub & 1;            // feature half
    int c = sub >> 1;           // texel column (0 = ix0, 1 = ix1)
    int nstride = (gridDim.x * blockDim.x) >> 2;

    for (int n = tid >> 2; n < N; n += nstride) {
        // ---- per-point setup (amortized over 3 planes x 2 levels) ----
        float xc0 = __ldg(&x[3 * n + 0]);
        float xc1 = __ldg(&x[3 * n + 1]);
        float xc2 = __ldg(&x[3 * n + 2]);

        float lvl = fminf(fmaxf(__ldg(&level[n]), 0.0f), (float)(NLV - 1));
        int   l0  = min((int)lvl, NLV - 2);
        float fr  = lvl - (float)l0;
        float w_lvl0 = 1.0f - fr;

        for (int p = 0; p < 3; p++) {
            float u = (p == 0) ? xc1 : xc0;
            float v = (p == 2) ? xc1 : xc2;

            float acc[8] = {0.f, 0.f, 0.f, 0.f, 0.f, 0.f, 0.f, 0.f};

            #pragma unroll
            for (int k = 0; k < 2; k++) {
                int   l = l0 + k;
                float w = k ? fr : w_lvl0;
                int   S = 512 >> l;

                float px = u * (float)S - 0.5f;
                float py = v * (float)S - 0.5f;
                float fx = floorf(px);
                float fy = floorf(py);
                int ix0 = (int)fx;
                int iy0 = (int)fy;
                int ix1 = min(ix0 + 1, S - 1);
                int iy1 = min(iy0 + 1, S - 1);
                ix0 = max(ix0, 0);
                iy0 = max(iy0, 0);
                float ax = px - fx;
                float ay = py - fy;

                int   ixc = c ? ix1 : ix0;
                float bx  = c ? ax  : 1.0f - ax;

                long e0 = (long)(iy0 * S + ixc) * 16 + h * 8;
                long e1 = (long)(iy1 * S + ixc) * 16 + h * 8;

                float4 r0, r1;
                if (l >= 4) {
                    const __half* b = s_top + (c_offh[l] - L4_OFF)
                                    + (long)p * S * S * 16;
                    r0 = *(const float4*)(b + e0);
                    r1 = *(const float4*)(b + e1);
                } else {
                    const __half* b = g_pyrh + c_offh[l]
                                    + (long)p * S * S * 16;
                    r0 = __ldg((const float4*)(b + e0));
                    r1 = __ldg((const float4*)(b + e1));
                }

                float w0 = w * bx * (1.0f - ay);
                float w1 = w * bx * ay;

                #define ACCQ(wgt, raw) { const __half2* _hp = (const __half2*)&(raw); \
                    float2 _f0 = __half22float2(_hp[0]); float2 _f1 = __half22float2(_hp[1]); \
                    float2 _f2 = __half22float2(_hp[2]); float2 _f3 = __half22float2(_hp[3]); \
                    acc[0] = fmaf(wgt, _f0.x, acc[0]); acc[1] = fmaf(wgt, _f0.y, acc[1]); \
                    acc[2] = fmaf(wgt, _f1.x, acc[2]); acc[3] = fmaf(wgt, _f1.y, acc[3]); \
                    acc[4] = fmaf(wgt, _f2.x, acc[4]); acc[5] = fmaf(wgt, _f2.y, acc[5]); \
                    acc[6] = fmaf(wgt, _f3.x, acc[6]); acc[7] = fmaf(wgt, _f3.y, acc[7]); }
                ACCQ(w0, r0); ACCQ(w1, r1);
                #undef ACCQ
            }

            // combine c-partners (lanes differing in bit 1; same n -> jointly active)
            unsigned m = __activemask();
            #pragma unroll
            for (int i = 0; i < 8; i++)
                acc[i] += __shfl_xor_sync(m, acc[i], 2);

            float4 lo = make_float4(acc[0], acc[1], acc[2], acc[3]);
            float4 hi = make_float4(acc[4], acc[5], acc[6], acc[7]);
            float4 sv = c ? hi : lo;
            ((float4*)(out + (long)n * 48 + p * 16 + h * 8))[c] = sv;
        }
    }
}

// ---------------------------------------------------------------------------
extern "C" void kernel_launch(void* const* d_in, const int* in_sizes, int n_in,
                              void* d_out, int out_size) {
    const float* x     = (const float*)d_in[0];
    const float* level = (const float*)d_in[1];
    const float* fm    = (const float*)d_in[2];
    float* out = (float*)d_out;
    int N = in_sizes[0] / 3;

    // K1: level 0 convert + level 1 build
    {
        int total = 3 * 256 * 256 * 4;
        k1_l0_l1<<<(total + 255) / 256, 256>>>(fm);
    }
    // K2: levels 2..7
    {
        int total_threads = 258048 + (3072 + 768 + 192) * 32;
        k2_levels<<<(total_threads + 255) / 256, 256>>>();
    }
    // Dummy: aligns ncu slot 5 onto the sampler
    dummy_slot<<<1, 1>>>();
    // S: persistent sampler, 130.5 KB dynamic smem
    {
        const int smem_bytes = SMEM_HALVES * 2;   // 130,560
        cudaFuncSetAttribute(trimip_sample,
                             cudaFuncAttributeMaxDynamicSharedMemorySize,
                             smem_bytes);
        trimip_sample<<<148, 1024, smem_bytes>>>(x, level, out, N);
    }
}

// round 16
// speedup vs baseline: 1.3864x; 1.1261x over previous
#include <cuda_runtime.h>
#include <cuda_fp16.h>

// TriMip encoding v9: v8 structure + fp16 HFMA2 accumulation, fp16 partner
// combine, and pure 32-bit offset arithmetic in the sampler hot loop.

#define NLV 8

__device__ float g_l1[3145728];           // fp32 level-1 scratch (12.6 MB)
__device__ __half g_pyrh[16776960];       // fp16 pyramid levels 0..7 (33.5 MB)

__constant__ int c_offh[8] = {0, 12582912, 15728640, 16515072, 16711680,
                              16760832, 16773120, 16776192};

#define L4_OFF      16711680              // c_offh[4]
#define SMEM_HALVES 65280                 // levels 4..7 halves (130,560 B)

// ---------------------------------------------------------------------------
// K1: one thread per level-1 quad (3*256*256*4 threads).
__global__ void __launch_bounds__(256) k1_l0_l1(const float* __restrict__ fm) {
    int t = blockIdx.x * blockDim.x + threadIdx.x;
    const int total = 3 * 256 * 256 * 4;
    if (t >= total) return;
    int q   = t & 3;
    int idx = t >> 2;
    int xo  = idx & 255; idx >>= 8;
    int yo  = idx & 255;
    int pl  = idx >> 8;

    const float4* src = (const float4*)fm;
    int y0 = 2 * yo, x0 = 2 * xo;
    int b00 = ((pl * 512 + y0) * 512 + x0) * 4 + q;
    float4 a = __ldg(src + b00);
    float4 b = __ldg(src + b00 + 4);
    float4 c = __ldg(src + b00 + 512 * 4);
    float4 d = __ldg(src + b00 + 512 * 4 + 4);

    uint2* l0h = (uint2*)g_pyrh;
    uint2 pa, pb, pc, pd;
    #define PACKQ(dst, v) { __half2 _h0 = __floats2half2_rn((v).x, (v).y); \
                            __half2 _h1 = __floats2half2_rn((v).z, (v).w); \
                            (dst).x = *(unsigned*)&_h0; (dst).y = *(unsigned*)&_h1; }
    PACKQ(pa, a); PACKQ(pb, b); PACKQ(pc, c); PACKQ(pd, d);
    l0h[b00]               = pa;
    l0h[b00 + 4]           = pb;
    l0h[b00 + 512 * 4]     = pc;
    l0h[b00 + 512 * 4 + 4] = pd;

    float4 o;
    o.x = (a.x + b.x + c.x + d.x) * 0.25f;
    o.y = (a.y + b.y + c.y + d.y) * 0.25f;
    o.z = (a.z + b.z + c.z + d.z) * 0.25f;
    o.w = (a.w + b.w + c.w + d.w) * 0.25f;

    int l1i = ((pl * 256 + yo) * 256 + xo) * 4 + q;
    ((float4*)g_l1)[l1i] = o;
    uint2 po; PACKQ(po, o);
    ((uint2*)(g_pyrh + c_offh[1]))[l1i] = po;
    #undef PACKQ
}

// ---------------------------------------------------------------------------
// K2: levels 2..7 from fp32 level1 by flat box mean.
__global__ void __launch_bounds__(256) k2_levels(void) {
    const int PT_L2 = 3 * 128 * 128 * 4;
    const int PT_L3 = 3 * 64 * 64 * 4;
    const int PT_L4 = 3 * 32 * 32 * 4;
    const int PT_TOTAL = PT_L2 + PT_L3 + PT_L4;
    const int PW_L5 = 3 * 16 * 16 * 4;
    const int PW_L6 = 3 * 8 * 8 * 4;
    const int PW_L7 = 3 * 4 * 4 * 4;

    int t = blockIdx.x * blockDim.x + threadIdx.x;
    const float4* l1 = (const float4*)g_l1;

    if (t < PT_TOTAL) {
        int l, rem = t;
        if (rem < PT_L2) l = 2;
        else if (rem < PT_L2 + PT_L3) { l = 3; rem -= PT_L2; }
        else { l = 4; rem -= PT_L2 + PT_L3; }
        int S = 512 >> l;
        int B = 1 << (l - 1);
        int q = rem & 3; int idx = rem >> 2;
        int x = idx % S; idx /= S;
        int y = idx % S;
        int pl = idx / S;

        float4 acc = make_float4(0.f, 0.f, 0.f, 0.f);
        int ybase = y * B, xbase = x * B;
        for (int by = 0; by < B; by++) {
            int row = ((pl * 256 + ybase + by) * 256 + xbase) * 4 + q;
            for (int bx = 0; bx < B; bx++) {
                float4 v = __ldg(l1 + row + bx * 4);
                acc.x += v.x; acc.y += v.y; acc.z += v.z; acc.w += v.w;
            }
        }
        float inv = 1.0f / (float)(B * B);
        acc.x *= inv; acc.y *= inv; acc.z *= inv; acc.w *= inv;
        __half2 h0 = __floats2half2_rn(acc.x, acc.y);
        __half2 h1 = __floats2half2_rn(acc.z, acc.w);
        uint2 po; po.x = *(unsigned*)&h0; po.y = *(unsigned*)&h1;
        ((uint2*)(g_pyrh + c_offh[l]))[((pl * S + y) * S + x) * 4 + q] = po;
        return;
    }

    int w = (t - PT_TOTAL) >> 5;
    int lane = t & 31;
    int l, rem = w;
    if (rem < PW_L5) l = 5;
    else if (rem < PW_L5 + PW_L6) { l = 6; rem -= PW_L5; }
    else if (rem < PW_L5 + PW_L6 + PW_L7) { l = 7; rem -= PW_L5 + PW_L6; }
    else return;

    int S = 512 >> l;
    int B = 1 << (l - 1);
    int nbox = B * B;
    int q = rem & 3; int idx = rem >> 2;
    int x = idx % S; idx /= S;
    int y = idx % S;
    int pl = idx / S;

    float4 acc = make_float4(0.f, 0.f, 0.f, 0.f);
    for (int j = lane; j < nbox; j += 32) {
        int by = j / B, bx = j - by * B;
        int e = ((pl * 256 + y * B + by) * 256 + x * B + bx) * 4 + q;
        float4 v = __ldg(l1 + e);
        acc.x += v.x; acc.y += v.y; acc.z += v.z; acc.w += v.w;
    }
    #pragma unroll
    for (int off = 16; off > 0; off >>= 1) {
        acc.x += __shfl_down_sync(0xffffffffu, acc.x, off);
        acc.y += __shfl_down_sync(0xffffffffu, acc.y, off);
        acc.z += __shfl_down_sync(0xffffffffu, acc.z, off);
        acc.w += __shfl_down_sync(0xffffffffu, acc.w, off);
    }
    if (lane == 0) {
        float inv = 1.0f / (float)nbox;
        acc.x *= inv; acc.y *= inv; acc.z *= inv; acc.w *= inv;
        __half2 h0 = __floats2half2_rn(acc.x, acc.y);
        __half2 h1 = __floats2half2_rn(acc.z, acc.w);
        uint2 po; po.x = *(unsigned*)&h0; po.y = *(unsigned*)&h1;
        ((uint2*)(g_pyrh + c_offh[l]))[((pl * S + y) * S + x) * 4 + q] = po;
    }
}

// ---------------------------------------------------------------------------
// Dummy no-op: shifts the ncu capture slot so slot 5 = trimip_sample.
__global__ void dummy_slot(void) {}

// ---------------------------------------------------------------------------
// Sampler v9: thread-quad per point (h = tid&1 feature half, c = (tid>>1)&1
// texel column). fp16 HFMA2 accumulation, fp16 shfl-combine, int offsets.
__global__ void __launch_bounds__(1024, 1) trimip_sample(
    const float* __restrict__ x,
    const float* __restrict__ level,
    float* __restrict__ out,
    int N)
{
    extern __shared__ __align__(16) __half s_top[];   // SMEM_HALVES

    // stage levels 4..7 (contiguous in g_pyrh from L4_OFF)
    {
        const float4* src = (const float4*)(g_pyrh + L4_OFF);
        float4* dst = (float4*)s_top;
        for (int i = threadIdx.x; i < SMEM_HALVES / 8; i += blockDim.x)
            dst[i] = __ldg(src + i);
    }
    __syncthreads();

    int tid = blockIdx.x * blockDim.x + threadIdx.x;
    int sub = tid & 3;
    int h = sub & 1;            // feature half
    int c = sub >> 1;           // texel column (0 = ix0, 1 = ix1)
    int h8 = h * 8;
    int nstride = (gridDim.x * blockDim.x) >> 2;

    const __half2 hz = __float2half2_rn(0.0f);

    for (int n = tid >> 2; n < N; n += nstride) {
        // ---- per-point setup ----
        float xc0 = __ldg(&x[3 * n + 0]);
        float xc1 = __ldg(&x[3 * n + 1]);
        float xc2 = __ldg(&x[3 * n + 2]);

        float lvl = fminf(fmaxf(__ldg(&level[n]), 0.0f), (float)(NLV - 1));
        int   l0  = min((int)lvl, NLV - 2);
        float fr  = lvl - (float)l0;
        float wl0 = 1.0f - fr;

        for (int p = 0; p < 3; p++) {
            float u = (p == 0) ? xc1 : xc0;
            float v = (p == 2) ? xc1 : xc2;

            __half2 a0 = hz, a1 = hz, a2 = hz, a3 = hz;

            #pragma unroll
            for (int k = 0; k < 2; k++) {
                int   l = l0 + k;
                float w = k ? fr : wl0;
                int   S = 512 >> l;

                float px = u * (float)S - 0.5f;
                float py = v * (float)S - 0.5f;
                float fx = floorf(px);
                float fy = floorf(py);
                int ix0 = (int)fx;
                int iy0 = (int)fy;
                int ix1 = min(ix0 + 1, S - 1);
                int iy1 = min(iy0 + 1, S - 1);
                ix0 = max(ix0, 0);
                iy0 = max(iy0, 0);
                float ax = px - fx;
                float ay = py - fy;

                int   ixc = c ? ix1 : ix0;
                float bx  = c ? ax  : 1.0f - ax;

                int e0 = (iy0 * S + ixc) * 16 + h8;
                int e1 = (iy1 * S + ixc) * 16 + h8;

                __half2 w0 = __float2half2_rn(w * bx * (1.0f - ay));
                __half2 w1 = __float2half2_rn(w * bx * ay);

                float4 r0, r1;
                if (l >= 4) {
                    const __half* b = s_top + (c_offh[l] - L4_OFF) + p * S * S * 16;
                    r0 = *(const float4*)(b + e0);
                    r1 = *(const float4*)(b + e1);
                } else {
                    const __half* b = g_pyrh + c_offh[l] + p * S * S * 16;
                    r0 = __ldg((const float4*)(b + e0));
                    r1 = __ldg((const float4*)(b + e1));
                }

                const __half2* q0 = (const __half2*)&r0;
                const __half2* q1 = (const __half2*)&r1;
                a0 = __hfma2(q0[0], w0, a0); a0 = __hfma2(q1[0], w1, a0);
                a1 = __hfma2(q0[1], w0, a1); a1 = __hfma2(q1[1], w1, a1);
                a2 = __hfma2(q0[2], w0, a2); a2 = __hfma2(q1[2], w1, a2);
                a3 = __hfma2(q0[3], w0, a3); a3 = __hfma2(q1[3], w1, a3);
            }

            // combine c-partners (xor lane bit 1; same n -> jointly active)
            unsigned m = __activemask();
            unsigned u0 = __shfl_xor_sync(m, *(unsigned*)&a0, 2);
            unsigned u1 = __shfl_xor_sync(m, *(unsigned*)&a1, 2);
            unsigned u2 = __shfl_xor_sync(m, *(unsigned*)&a2, 2);
            unsigned u3 = __shfl_xor_sync(m, *(unsigned*)&a3, 2);
            a0 = __hadd2(a0, *(__half2*)&u0);
            a1 = __hadd2(a1, *(__half2*)&u1);
            a2 = __hadd2(a2, *(__half2*)&u2);
            a3 = __hadd2(a3, *(__half2*)&u3);

            float4 sv;
            if (c) {
                float2 f2 = __half22float2(a2);
                float2 f3 = __half22float2(a3);
                sv = make_float4(f2.x, f2.y, f3.x, f3.y);
            } else {
                float2 f0 = __half22float2(a0);
                float2 f1 = __half22float2(a1);
                sv = make_float4(f0.x, f0.y, f1.x, f1.y);
            }
            ((float4*)(out + n * 48 + p * 16 + h8))[c] = sv;
        }
    }
}

// ---------------------------------------------------------------------------
extern "C" void kernel_launch(void* const* d_in, const int* in_sizes, int n_in,
                              void* d_out, int out_size) {
    const float* x     = (const float*)d_in[0];
    const float* level = (const float*)d_in[1];
    const float* fm    = (const float*)d_in[2];
    float* out = (float*)d_out;
    int N = in_sizes[0] / 3;

    // K1: level 0 convert + level 1 build
    {
        int total = 3 * 256 * 256 * 4;
        k1_l0_l1<<<(total + 255) / 256, 256>>>(fm);
    }
    // K2: levels 2..7
    {
        int total_threads = 258048 + (3072 + 768 + 192) * 32;
        k2_levels<<<(total_threads + 255) / 256, 256>>>();
    }
    // Dummy: aligns ncu slot 5 onto the sampler
    dummy_slot<<<1, 1>>>();
    // S: persistent sampler, 130.5 KB dynamic smem
    {
        const int smem_bytes = SMEM_HALVES * 2;   // 130,560
        cudaFuncSetAttribute(trimip_sample,
                             cudaFuncAttributeMaxDynamicSharedMemorySize,
                             smem_bytes);
        trimip_sample<<<148, 1024, smem_bytes>>>(x, level, out, N);
    }
}

// round 17
// speedup vs baseline: 1.4180x; 1.0228x over previous
#include <cuda_runtime.h>
#include <cuda_fp16.h>

// TriMip encoding v10: all-LDG sampler (no smem) — levels 4..7 (130.5 KB)
// live in L1 (228 KB, zero carveout). Single load path (no divergence),
// <=42 regs -> 48 warps/SM. Quad-merged 64B loads + HFMA2 accumulation.

#define NLV 8

__device__ float g_l1[3145728];           // fp32 level-1 scratch (12.6 MB)
__device__ __half g_pyrh[16776960];       // fp16 pyramid levels 0..7 (33.5 MB)

__constant__ int c_offh[8] = {0, 12582912, 15728640, 16515072, 16711680,
                              16760832, 16773120, 16776192};

// ---------------------------------------------------------------------------
// K1: one thread per level-1 quad (3*256*256*4 threads).
__global__ void __launch_bounds__(256) k1_l0_l1(const float* __restrict__ fm) {
    int t = blockIdx.x * blockDim.x + threadIdx.x;
    const int total = 3 * 256 * 256 * 4;
    if (t >= total) return;
    int q   = t & 3;
    int idx = t >> 2;
    int xo  = idx & 255; idx >>= 8;
    int yo  = idx & 255;
    int pl  = idx >> 8;

    const float4* src = (const float4*)fm;
    int y0 = 2 * yo, x0 = 2 * xo;
    int b00 = ((pl * 512 + y0) * 512 + x0) * 4 + q;
    float4 a = __ldg(src + b00);
    float4 b = __ldg(src + b00 + 4);
    float4 c = __ldg(src + b00 + 512 * 4);
    float4 d = __ldg(src + b00 + 512 * 4 + 4);

    uint2* l0h = (uint2*)g_pyrh;
    uint2 pa, pb, pc, pd;
    #define PACKQ(dst, v) { __half2 _h0 = __floats2half2_rn((v).x, (v).y); \
                            __half2 _h1 = __floats2half2_rn((v).z, (v).w); \
                            (dst).x = *(unsigned*)&_h0; (dst).y = *(unsigned*)&_h1; }
    PACKQ(pa, a); PACKQ(pb, b); PACKQ(pc, c); PACKQ(pd, d);
    l0h[b00]               = pa;
    l0h[b00 + 4]           = pb;
    l0h[b00 + 512 * 4]     = pc;
    l0h[b00 + 512 * 4 + 4] = pd;

    float4 o;
    o.x = (a.x + b.x + c.x + d.x) * 0.25f;
    o.y = (a.y + b.y + c.y + d.y) * 0.25f;
    o.z = (a.z + b.z + c.z + d.z) * 0.25f;
    o.w = (a.w + b.w + c.w + d.w) * 0.25f;

    int l1i = ((pl * 256 + yo) * 256 + xo) * 4 + q;
    ((float4*)g_l1)[l1i] = o;
    uint2 po; PACKQ(po, o);
    ((uint2*)(g_pyrh + c_offh[1]))[l1i] = po;
    #undef PACKQ
}

// ---------------------------------------------------------------------------
// K2: levels 2..7 from fp32 level1 by flat box mean.
__global__ void __launch_bounds__(256) k2_levels(void) {
    const int PT_L2 = 3 * 128 * 128 * 4;
    const int PT_L3 = 3 * 64 * 64 * 4;
    const int PT_L4 = 3 * 32 * 32 * 4;
    const int PT_TOTAL = PT_L2 + PT_L3 + PT_L4;
    const int PW_L5 = 3 * 16 * 16 * 4;
    const int PW_L6 = 3 * 8 * 8 * 4;
    const int PW_L7 = 3 * 4 * 4 * 4;

    int t = blockIdx.x * blockDim.x + threadIdx.x;
    const float4* l1 = (const float4*)g_l1;

    if (t < PT_TOTAL) {
        int l, rem = t;
        if (rem < PT_L2) l = 2;
        else if (rem < PT_L2 + PT_L3) { l = 3; rem -= PT_L2; }
        else { l = 4; rem -= PT_L2 + PT_L3; }
        int S = 512 >> l;
        int B = 1 << (l - 1);
        int q = rem & 3; int idx = rem >> 2;
        int x = idx % S; idx /= S;
        int y = idx % S;
        int pl = idx / S;

        float4 acc = make_float4(0.f, 0.f, 0.f, 0.f);
        int ybase = y * B, xbase = x * B;
        for (int by = 0; by < B; by++) {
            int row = ((pl * 256 + ybase + by) * 256 + xbase) * 4 + q;
            for (int bx = 0; bx < B; bx++) {
                float4 v = __ldg(l1 + row + bx * 4);
                acc.x += v.x; acc.y += v.y; acc.z += v.z; acc.w += v.w;
            }
        }
        float inv = 1.0f / (float)(B * B);
        acc.x *= inv; acc.y *= inv; acc.z *= inv; acc.w *= inv;
        __half2 h0 = __floats2half2_rn(acc.x, acc.y);
        __half2 h1 = __floats2half2_rn(acc.z, acc.w);
        uint2 po; po.x = *(unsigned*)&h0; po.y = *(unsigned*)&h1;
        ((uint2*)(g_pyrh + c_offh[l]))[((pl * S + y) * S + x) * 4 + q] = po;
        return;
    }

    int w = (t - PT_TOTAL) >> 5;
    int lane = t & 31;
    int l, rem = w;
    if (rem < PW_L5) l = 5;
    else if (rem < PW_L5 + PW_L6) { l = 6; rem -= PW_L5; }
    else if (rem < PW_L5 + PW_L6 + PW_L7) { l = 7; rem -= PW_L5 + PW_L6; }
    else return;

    int S = 512 >> l;
    int B = 1 << (l - 1);
    int nbox = B * B;
    int q = rem & 3; int idx = rem >> 2;
    int x = idx % S; idx /= S;
    int y = idx % S;
    int pl = idx / S;

    float4 acc = make_float4(0.f, 0.f, 0.f, 0.f);
    for (int j = lane; j < nbox; j += 32) {
        int by = j / B, bx = j - by * B;
        int e = ((pl * 256 + y * B + by) * 256 + x * B + bx) * 4 + q;
        float4 v = __ldg(l1 + e);
        acc.x += v.x; acc.y += v.y; acc.z += v.z; acc.w += v.w;
    }
    #pragma unroll
    for (int off = 16; off > 0; off >>= 1) {
        acc.x += __shfl_down_sync(0xffffffffu, acc.x, off);
        acc.y += __shfl_down_sync(0xffffffffu, acc.y, off);
        acc.z += __shfl_down_sync(0xffffffffu, acc.z, off);
        acc.w += __shfl_down_sync(0xffffffffu, acc.w, off);
    }
    if (lane == 0) {
        float inv = 1.0f / (float)nbox;
        acc.x *= inv; acc.y *= inv; acc.z *= inv; acc.w *= inv;
        __half2 h0 = __floats2half2_rn(acc.x, acc.y);
        __half2 h1 = __floats2half2_rn(acc.z, acc.w);
        uint2 po; po.x = *(unsigned*)&h0; po.y = *(unsigned*)&h1;
        ((uint2*)(g_pyrh + c_offh[l]))[((pl * S + y) * S + x) * 4 + q] = po;
    }
}

// ---------------------------------------------------------------------------
// Dummy no-op: shifts the ncu capture slot so slot 5 = trimip_sample.
__global__ void dummy_slot(void) {}

// ---------------------------------------------------------------------------
// Sampler v10: thread-quad per point (h = tid&1 feature half, c = (tid>>1)&1
// texel column). Single __ldg path for all levels; HFMA2 accumulation;
// 32-bit offsets; only the owned texel column is computed.
__global__ void __launch_bounds__(256, 6) trimip_sample(
    const float* __restrict__ x,
    const float* __restrict__ level,
    float* __restrict__ out,
    int N)
{
    int tid = blockIdx.x * blockDim.x + threadIdx.x;
    if (tid >= N * 4) return;
    int sub = tid & 3;
    int h = sub & 1;            // feature half
    int c = sub >> 1;           // texel column (0 = ix0, 1 = ix1)
    int h8 = h * 8;
    int n = tid >> 2;

    // ---- per-point setup ----
    float xc0 = __ldg(&x[3 * n + 0]);
    float xc1 = __ldg(&x[3 * n + 1]);
    float xc2 = __ldg(&x[3 * n + 2]);

    float lvl = fminf(fmaxf(__ldg(&level[n]), 0.0f), (float)(NLV - 1));
    int   l0  = min((int)lvl, NLV - 2);
    float fr  = lvl - (float)l0;
    float wl0 = 1.0f - fr;

    const __half2 hz = __float2half2_rn(0.0f);

    for (int p = 0; p < 3; p++) {
        float u = (p == 0) ? xc1 : xc0;
        float v = (p == 2) ? xc1 : xc2;

        __half2 a0 = hz, a1 = hz, a2 = hz, a3 = hz;

        #pragma unroll
        for (int k = 0; k < 2; k++) {
            int   l = l0 + k;
            float w = k ? fr : wl0;
            int   S = 512 >> l;

            float px = u * (float)S - 0.5f;
            float py = v * (float)S - 0.5f;
            float fx = floorf(px);
            float fy = floorf(py);
            int ix0 = (int)fx;
            int iy0 = (int)fy;
            int iy1 = min(iy0 + 1, S - 1);
            iy0 = max(iy0, 0);
            float ax = px - fx;
            float ay = py - fy;

            // only the owned texel column
            int ixc = min(max(ix0 + c, 0), S - 1);
            float bx = c ? ax : 1.0f - ax;

            const __half* b = g_pyrh + c_offh[l] + p * S * S * 16;
            int e0 = (iy0 * S + ixc) * 16 + h8;
            int e1 = (iy1 * S + ixc) * 16 + h8;

            __half2 w0 = __float2half2_rn(w * bx * (1.0f - ay));
            __half2 w1 = __float2half2_rn(w * bx * ay);

            float4 r0 = __ldg((const float4*)(b + e0));
            float4 r1 = __ldg((const float4*)(b + e1));

            const __half2* q0 = (const __half2*)&r0;
            const __half2* q1 = (const __half2*)&r1;
            a0 = __hfma2(q0[0], w0, a0); a0 = __hfma2(q1[0], w1, a0);
            a1 = __hfma2(q0[1], w0, a1); a1 = __hfma2(q1[1], w1, a1);
            a2 = __hfma2(q0[2], w0, a2); a2 = __hfma2(q1[2], w1, a2);
            a3 = __hfma2(q0[3], w0, a3); a3 = __hfma2(q1[3], w1, a3);
        }

        // combine c-partners (xor lane bit 1; same n -> jointly active)
        unsigned m = __activemask();
        unsigned u0 = __shfl_xor_sync(m, *(unsigned*)&a0, 2);
        unsigned u1 = __shfl_xor_sync(m, *(unsigned*)&a1, 2);
        unsigned u2 = __shfl_xor_sync(m, *(unsigned*)&a2, 2);
        unsigned u3 = __shfl_xor_sync(m, *(unsigned*)&a3, 2);
        a0 = __hadd2(a0, *(__half2*)&u0);
        a1 = __hadd2(a1, *(__half2*)&u1);
        a2 = __hadd2(a2, *(__half2*)&u2);
        a3 = __hadd2(a3, *(__half2*)&u3);

        float4 sv;
        if (c) {
            float2 f2 = __half22float2(a2);
            float2 f3 = __half22float2(a3);
            sv = make_float4(f2.x, f2.y, f3.x, f3.y);
        } else {
            float2 f0 = __half22float2(a0);
            float2 f1 = __half22float2(a1);
            sv = make_float4(f0.x, f0.y, f1.x, f1.y);
        }
        ((float4*)(out + n * 48 + p * 16 + h8))[c] = sv;
    }
}

// ---------------------------------------------------------------------------
extern "C" void kernel_launch(void* const* d_in, const int* in_sizes, int n_in,
                              void* d_out, int out_size) {
    const float* x     = (const float*)d_in[0];
    const float* level = (const float*)d_in[1];
    const float* fm    = (const float*)d_in[2];
    float* out = (float*)d_out;
    int N = in_sizes[0] / 3;

    // K1: level 0 convert + level 1 build
    {
        int total = 3 * 256 * 256 * 4;
        k1_l0_l1<<<(total + 255) / 256, 256>>>(fm);
    }
    // K2: levels 2..7
    {
        int total_threads = 258048 + (3072 + 768 + 192) * 32;
        k2_levels<<<(total_threads + 255) / 256, 256>>>();
    }
    // Dummy: aligns ncu slot 5 onto the sampler
    dummy_slot<<<1, 1>>>();
    // S: sampler, no smem, 48 warps/SM target
    {
        int total = N * 4;
        trimip_sample<<<(total + 255) / 256, 256>>>(x, level, out, N);
    }
}